// round 1
// baseline (speedup 1.0000x reference)
#include <cuda_runtime.h>
#include <cstddef>

// Problem constants (fixed by the reference)
#define N_NODES 100000
#define N_EDGES 1600000
#define F_IN    64
#define HIDDEN  128
#define N_GRAPHS 1024
#define EPS 1e-5f

// ---------------- static scratch (no allocation allowed) ----------------
__device__ float g_h1[(size_t)N_NODES * HIDDEN];      // 51.2 MB
__device__ float g_h2[(size_t)N_NODES * HIDDEN];      // 51.2 MB
__device__ float g_agg[(size_t)N_NODES * HIDDEN];     // 51.2 MB (also used for D=64)
__device__ float g_pooled[(size_t)N_GRAPHS * HIDDEN];
__device__ float g_cnt[N_GRAPHS];

// ---------------- edge scatter: agg[dst] += ew * h[src] -----------------
// One warp per edge. D=128 -> float4 per lane; D=64 -> float2 per lane.
template <int D>
__global__ void scatter_kernel(const float* __restrict__ h,
                               const int* __restrict__ src,
                               const int* __restrict__ dst,
                               const float* __restrict__ ew,
                               float* __restrict__ agg)
{
    int w = (blockIdx.x * blockDim.x + threadIdx.x) >> 5;
    int lane = threadIdx.x & 31;
    if (w >= N_EDGES) return;
    int s = __ldg(src + w);
    int d = __ldg(dst + w);
    float e = __ldg(ew + w);

    if (D == 128) {
        float4 v = *(reinterpret_cast<const float4*>(h + (size_t)s * 128) + lane);
        float* ap = agg + (size_t)d * 128 + lane * 4;
        atomicAdd(ap + 0, v.x * e);
        atomicAdd(ap + 1, v.y * e);
        atomicAdd(ap + 2, v.z * e);
        atomicAdd(ap + 3, v.w * e);
    } else { // D == 64
        float2 v = *(reinterpret_cast<const float2*>(h + (size_t)s * 64) + lane);
        float* ap = agg + (size_t)d * 64 + lane * 2;
        atomicAdd(ap + 0, v.x * e);
        atomicAdd(ap + 1, v.y * e);
    }
}

// ---------- fused dual-GEMM + bias + BN(inference) + ReLU ----------------
// out[n, j] = relu( ((agg[n,:]@Wr[:,j] + h[n,:]@Wo[:,j] + br[j]) - m[j]) * g[j]*rsqrt(v[j]+eps) + b[j] )
// Block: 128 threads (one per output column j), 32-node tile staged in SMEM.
template <int DIN>
__global__ void conv_gemm_kernel(const float* __restrict__ agg,
                                 const float* __restrict__ h,
                                 const float* __restrict__ Wr,
                                 const float* __restrict__ br,
                                 const float* __restrict__ Wo,
                                 const float* __restrict__ bng,
                                 const float* __restrict__ bnb,
                                 const float* __restrict__ bnm,
                                 const float* __restrict__ bnv,
                                 float* __restrict__ out)
{
    __shared__ float sA[32 * DIN];
    __shared__ float sH[32 * DIN];
    const int tid = threadIdx.x;            // 0..127 output column
    const int n0  = blockIdx.x * 32;        // N_NODES = 3125 * 32 exactly

    const float* aggp = agg + (size_t)n0 * DIN;
    const float* hp   = h   + (size_t)n0 * DIN;
    #pragma unroll 4
    for (int i = tid; i < 32 * DIN; i += 128) {
        sA[i] = aggp[i];
        sH[i] = hp[i];
    }
    __syncthreads();

    float acc[32];
    #pragma unroll
    for (int mm = 0; mm < 32; mm++) acc[mm] = 0.f;

    // K-chunks of 4 so node-tile reads are 128-bit LDS (broadcast across warp).
    #pragma unroll 2
    for (int k = 0; k < DIN; k += 4) {
        float wr0 = __ldg(Wr + (k + 0) * HIDDEN + tid);
        float wr1 = __ldg(Wr + (k + 1) * HIDDEN + tid);
        float wr2 = __ldg(Wr + (k + 2) * HIDDEN + tid);
        float wr3 = __ldg(Wr + (k + 3) * HIDDEN + tid);
        float wo0 = __ldg(Wo + (k + 0) * HIDDEN + tid);
        float wo1 = __ldg(Wo + (k + 1) * HIDDEN + tid);
        float wo2 = __ldg(Wo + (k + 2) * HIDDEN + tid);
        float wo3 = __ldg(Wo + (k + 3) * HIDDEN + tid);
        #pragma unroll
        for (int mm = 0; mm < 32; mm++) {
            float4 a = *reinterpret_cast<const float4*>(&sA[mm * DIN + k]);
            float4 x = *reinterpret_cast<const float4*>(&sH[mm * DIN + k]);
            float t = acc[mm];
            t = fmaf(a.x, wr0, t); t = fmaf(a.y, wr1, t);
            t = fmaf(a.z, wr2, t); t = fmaf(a.w, wr3, t);
            t = fmaf(x.x, wo0, t); t = fmaf(x.y, wo1, t);
            t = fmaf(x.z, wo2, t); t = fmaf(x.w, wo3, t);
            acc[mm] = t;
        }
    }

    const float scale = __ldg(bng + tid) * rsqrtf(__ldg(bnv + tid) + EPS);
    const float shift = (__ldg(br + tid) - __ldg(bnm + tid)) * scale + __ldg(bnb + tid);
    #pragma unroll
    for (int mm = 0; mm < 32; mm++) {
        float r = fmaf(acc[mm], scale, shift);
        out[(size_t)(n0 + mm) * HIDDEN + tid] = fmaxf(r, 0.f);
    }
}

// ---------------- mean-pool accumulation --------------------------------
__global__ void pool_kernel(const float* __restrict__ h,
                            const int* __restrict__ batch,
                            float* __restrict__ pooled,
                            float* __restrict__ cnt)
{
    int idx = blockIdx.x * blockDim.x + threadIdx.x;
    if (idx >= N_NODES * HIDDEN) return;
    int n = idx >> 7;      // / 128
    int c = idx & 127;
    int g = __ldg(batch + n);
    atomicAdd(pooled + (size_t)g * HIDDEN + c, h[idx]);
    if (c == 0) atomicAdd(cnt + g, 1.0f);
}

// ---------------- head: relu(pooled/cnt @ W1 + b1) @ W2 + b2 -------------
__global__ void head_kernel(const float* __restrict__ pooled,
                            const float* __restrict__ cnt,
                            const float* __restrict__ W1,
                            const float* __restrict__ b1,
                            const float* __restrict__ W2,
                            const float* __restrict__ b2,
                            float* __restrict__ out)
{
    __shared__ float sp[HIDDEN];
    __shared__ float sred[128];
    const int g = blockIdx.x;
    const int t = threadIdx.x;

    float inv = 1.0f / fmaxf(__ldg(cnt + g), 1.0f);
    sp[t] = pooled[(size_t)g * HIDDEN + t] * inv;
    __syncthreads();

    float val = 0.f;
    if (t < 64) {
        float acc = __ldg(b1 + t);
        #pragma unroll 8
        for (int k = 0; k < HIDDEN; k++)
            acc = fmaf(sp[k], __ldg(W1 + k * 64 + t), acc);
        val = fmaxf(acc, 0.f) * __ldg(W2 + t);
    }
    sred[t] = val;
    __syncthreads();
    for (int s = 64; s > 0; s >>= 1) {
        if (t < s) sred[t] += sred[t + s];
        __syncthreads();
    }
    if (t == 0) out[g] = sred[0] + __ldg(b2);
}

// -------------------------------------------------------------------------
extern "C" void kernel_launch(void* const* d_in, const int* in_sizes, int n_in,
                              void* d_out, int out_size)
{
    (void)in_sizes; (void)n_in;
    const float* x     = (const float*)d_in[0];
    const int*   ei    = (const int*)  d_in[1];
    const float* ea    = (const float*)d_in[2];
    const int*   batch = (const int*)  d_in[3];
    // layer l params at d_in[4 + l*7 + {0:rel_w,1:rel_b,2:root_w,3:bn_g,4:bn_b,5:bn_m,6:bn_v}]
    const float* P[21];
    for (int i = 0; i < 21; i++) P[i] = (const float*)d_in[4 + i];
    const float* head_w1 = (const float*)d_in[25];
    const float* head_b1 = (const float*)d_in[26];
    const float* head_w2 = (const float*)d_in[27];
    const float* head_b2 = (const float*)d_in[28];
    float* out = (float*)d_out;

    float *h1, *h2, *agg, *pooled, *cnt;
    cudaGetSymbolAddress((void**)&h1,     g_h1);
    cudaGetSymbolAddress((void**)&h2,     g_h2);
    cudaGetSymbolAddress((void**)&agg,    g_agg);
    cudaGetSymbolAddress((void**)&pooled, g_pooled);
    cudaGetSymbolAddress((void**)&cnt,    g_cnt);

    const int* src = ei;
    const int* dst = ei + N_EDGES;

    const int scat_blocks = (N_EDGES * 32) / 256;   // warp per edge, 8 warps/block
    const int gemm_blocks = N_NODES / 32;           // 3125

    // ---- Layer 0 (DIN = 64): x -> h1 ----
    cudaMemsetAsync(agg, 0, (size_t)N_NODES * F_IN * sizeof(float), 0);
    scatter_kernel<64><<<scat_blocks, 256>>>(x, src, dst, ea, agg);
    conv_gemm_kernel<64><<<gemm_blocks, 128>>>(agg, x,
        P[0], P[1], P[2], P[3], P[4], P[5], P[6], h1);

    // ---- Layer 1 (DIN = 128): h1 -> h2 ----
    cudaMemsetAsync(agg, 0, (size_t)N_NODES * HIDDEN * sizeof(float), 0);
    scatter_kernel<128><<<scat_blocks, 256>>>(h1, src, dst, ea, agg);
    conv_gemm_kernel<128><<<gemm_blocks, 128>>>(agg, h1,
        P[7], P[8], P[9], P[10], P[11], P[12], P[13], h2);

    // ---- Layer 2 (DIN = 128): h2 -> h1 ----
    cudaMemsetAsync(agg, 0, (size_t)N_NODES * HIDDEN * sizeof(float), 0);
    scatter_kernel<128><<<scat_blocks, 256>>>(h2, src, dst, ea, agg);
    conv_gemm_kernel<128><<<gemm_blocks, 128>>>(agg, h2,
        P[14], P[15], P[16], P[17], P[18], P[19], P[20], h1);

    // ---- Mean pool + head ----
    cudaMemsetAsync(pooled, 0, (size_t)N_GRAPHS * HIDDEN * sizeof(float), 0);
    cudaMemsetAsync(cnt,    0, (size_t)N_GRAPHS * sizeof(float), 0);
    pool_kernel<<<(N_NODES * HIDDEN + 255) / 256, 256>>>(h1, batch, pooled, cnt);
    head_kernel<<<N_GRAPHS, 128>>>(pooled, cnt, head_w1, head_b1, head_w2, head_b2, out);
}

// round 2
// speedup vs baseline: 2.2104x; 2.2104x over previous
#include <cuda_runtime.h>
#include <cstddef>

// Problem constants (fixed by the reference)
#define N_NODES 100000
#define N_EDGES 1600000
#define F_IN    64
#define HIDDEN  128
#define N_GRAPHS 1024
#define EPS 1e-5f

#define SCAN_BLK 256
#define N_SCAN_BLOCKS ((N_NODES + SCAN_BLK - 1) / SCAN_BLK)   // 391

// ---------------- static scratch (no allocation allowed) ----------------
__device__ float g_h1[(size_t)N_NODES * HIDDEN];      // 51.2 MB
__device__ float g_h2[(size_t)N_NODES * HIDDEN];      // 51.2 MB
__device__ float g_agg[(size_t)N_NODES * HIDDEN];     // 51.2 MB (also used for D=64)

__device__ int   g_deg[N_NODES];
__device__ int   g_incl[N_SCAN_BLOCKS * SCAN_BLK];
__device__ int   g_bsum[N_SCAN_BLOCKS];
__device__ int   g_boff[N_SCAN_BLOCKS];
__device__ int   g_rowptr[N_NODES + 1];
__device__ int   g_cursor[N_NODES];
__device__ int   g_csr_src[N_EDGES];
__device__ float g_csr_ew[N_EDGES];

// ======================= CSR build (by dst) ==============================
__global__ void hist_kernel(const int* __restrict__ dst, int* __restrict__ deg)
{
    int e = blockIdx.x * blockDim.x + threadIdx.x;
    if (e < N_EDGES) atomicAdd(deg + __ldg(dst + e), 1);
}

// inclusive scan of 256-elem chunks + block totals
__global__ void scan1_kernel(const int* __restrict__ deg,
                             int* __restrict__ incl, int* __restrict__ bsum)
{
    __shared__ int s[SCAN_BLK];
    int gid = blockIdx.x * SCAN_BLK + threadIdx.x;
    int v = (gid < N_NODES) ? deg[gid] : 0;
    s[threadIdx.x] = v;
    __syncthreads();
    #pragma unroll
    for (int off = 1; off < SCAN_BLK; off <<= 1) {
        int t = (threadIdx.x >= off) ? s[threadIdx.x - off] : 0;
        __syncthreads();
        s[threadIdx.x] += t;
        __syncthreads();
    }
    incl[gid] = s[threadIdx.x];
    if (threadIdx.x == SCAN_BLK - 1) bsum[blockIdx.x] = s[threadIdx.x];
}

// exclusive scan of the 391 block sums (single block of 512 threads)
__global__ void scan2_kernel(const int* __restrict__ bsum, int* __restrict__ boff)
{
    __shared__ int s[512];
    int t = threadIdx.x;
    s[t] = (t < N_SCAN_BLOCKS) ? bsum[t] : 0;
    __syncthreads();
    #pragma unroll
    for (int off = 1; off < 512; off <<= 1) {
        int v = (t >= off) ? s[t - off] : 0;
        __syncthreads();
        s[t] += v;
        __syncthreads();
    }
    if (t < N_SCAN_BLOCKS) boff[t] = s[t] - bsum[t];   // exclusive
}

__global__ void scan3_kernel(const int* __restrict__ deg,
                             const int* __restrict__ incl,
                             const int* __restrict__ boff,
                             int* __restrict__ rowptr)
{
    int i = blockIdx.x * blockDim.x + threadIdx.x;
    if (i < N_NODES)
        rowptr[i] = incl[i] - deg[i] + boff[i / SCAN_BLK];  // exclusive prefix
    if (i == 0) rowptr[N_NODES] = N_EDGES;
}

__global__ void fill_kernel(const int* __restrict__ src,
                            const int* __restrict__ dst,
                            const float* __restrict__ ew,
                            const int* __restrict__ rowptr,
                            int* __restrict__ cursor,
                            int* __restrict__ csr_src,
                            float* __restrict__ csr_ew)
{
    int e = blockIdx.x * blockDim.x + threadIdx.x;
    if (e >= N_EDGES) return;
    int d = __ldg(dst + e);
    int pos = atomicAdd(cursor + d, 1);
    int idx = __ldg(rowptr + d) + pos;
    csr_src[idx] = __ldg(src + e);
    csr_ew[idx]  = __ldg(ew + e);
}

// ================= gather: agg[n] = sum_e ew[e] * h[src[e]] ==============
// One warp per node; float4 (D=128) / float2 (D=64) per lane; edges unrolled x2.
template <int D>
__global__ void gather_kernel(const float* __restrict__ h,
                              const int* __restrict__ rowptr,
                              const int* __restrict__ csr_src,
                              const float* __restrict__ csr_ew,
                              float* __restrict__ agg)
{
    int node = (blockIdx.x * blockDim.x + threadIdx.x) >> 5;
    if (node >= N_NODES) return;
    int lane = threadIdx.x & 31;
    int beg = __ldg(rowptr + node);
    int end = __ldg(rowptr + node + 1);

    if (D == 128) {
        float4 acc = make_float4(0.f, 0.f, 0.f, 0.f);
        int i = beg;
        for (; i + 1 < end; i += 2) {
            int   s0 = __ldg(csr_src + i);
            int   s1 = __ldg(csr_src + i + 1);
            float e0 = __ldg(csr_ew + i);
            float e1 = __ldg(csr_ew + i + 1);
            float4 v0 = *(reinterpret_cast<const float4*>(h + (size_t)s0 * 128) + lane);
            float4 v1 = *(reinterpret_cast<const float4*>(h + (size_t)s1 * 128) + lane);
            acc.x = fmaf(v0.x, e0, acc.x); acc.y = fmaf(v0.y, e0, acc.y);
            acc.z = fmaf(v0.z, e0, acc.z); acc.w = fmaf(v0.w, e0, acc.w);
            acc.x = fmaf(v1.x, e1, acc.x); acc.y = fmaf(v1.y, e1, acc.y);
            acc.z = fmaf(v1.z, e1, acc.z); acc.w = fmaf(v1.w, e1, acc.w);
        }
        if (i < end) {
            int   s0 = __ldg(csr_src + i);
            float e0 = __ldg(csr_ew + i);
            float4 v0 = *(reinterpret_cast<const float4*>(h + (size_t)s0 * 128) + lane);
            acc.x = fmaf(v0.x, e0, acc.x); acc.y = fmaf(v0.y, e0, acc.y);
            acc.z = fmaf(v0.z, e0, acc.z); acc.w = fmaf(v0.w, e0, acc.w);
        }
        *(reinterpret_cast<float4*>(agg + (size_t)node * 128) + lane) = acc;
    } else { // D == 64
        float2 acc = make_float2(0.f, 0.f);
        int i = beg;
        for (; i + 1 < end; i += 2) {
            int   s0 = __ldg(csr_src + i);
            int   s1 = __ldg(csr_src + i + 1);
            float e0 = __ldg(csr_ew + i);
            float e1 = __ldg(csr_ew + i + 1);
            float2 v0 = *(reinterpret_cast<const float2*>(h + (size_t)s0 * 64) + lane);
            float2 v1 = *(reinterpret_cast<const float2*>(h + (size_t)s1 * 64) + lane);
            acc.x = fmaf(v0.x, e0, acc.x); acc.y = fmaf(v0.y, e0, acc.y);
            acc.x = fmaf(v1.x, e1, acc.x); acc.y = fmaf(v1.y, e1, acc.y);
        }
        if (i < end) {
            int   s0 = __ldg(csr_src + i);
            float e0 = __ldg(csr_ew + i);
            float2 v0 = *(reinterpret_cast<const float2*>(h + (size_t)s0 * 64) + lane);
            acc.x = fmaf(v0.x, e0, acc.x); acc.y = fmaf(v0.y, e0, acc.y);
        }
        *(reinterpret_cast<float2*>(agg + (size_t)node * 64) + lane) = acc;
    }
}

// ---------- fused dual-GEMM + bias + BN(inference) + ReLU ----------------
template <int DIN>
__global__ void conv_gemm_kernel(const float* __restrict__ agg,
                                 const float* __restrict__ h,
                                 const float* __restrict__ Wr,
                                 const float* __restrict__ br,
                                 const float* __restrict__ Wo,
                                 const float* __restrict__ bng,
                                 const float* __restrict__ bnb,
                                 const float* __restrict__ bnm,
                                 const float* __restrict__ bnv,
                                 float* __restrict__ out)
{
    __shared__ float sA[32 * DIN];
    __shared__ float sH[32 * DIN];
    const int tid = threadIdx.x;            // 0..127 output column
    const int n0  = blockIdx.x * 32;        // N_NODES = 3125 * 32 exactly

    const float* aggp = agg + (size_t)n0 * DIN;
    const float* hp   = h   + (size_t)n0 * DIN;
    #pragma unroll 4
    for (int i = tid; i < 32 * DIN; i += 128) {
        sA[i] = aggp[i];
        sH[i] = hp[i];
    }
    __syncthreads();

    float acc[32];
    #pragma unroll
    for (int mm = 0; mm < 32; mm++) acc[mm] = 0.f;

    #pragma unroll 2
    for (int k = 0; k < DIN; k += 4) {
        float wr0 = __ldg(Wr + (k + 0) * HIDDEN + tid);
        float wr1 = __ldg(Wr + (k + 1) * HIDDEN + tid);
        float wr2 = __ldg(Wr + (k + 2) * HIDDEN + tid);
        float wr3 = __ldg(Wr + (k + 3) * HIDDEN + tid);
        float wo0 = __ldg(Wo + (k + 0) * HIDDEN + tid);
        float wo1 = __ldg(Wo + (k + 1) * HIDDEN + tid);
        float wo2 = __ldg(Wo + (k + 2) * HIDDEN + tid);
        float wo3 = __ldg(Wo + (k + 3) * HIDDEN + tid);
        #pragma unroll
        for (int mm = 0; mm < 32; mm++) {
            float4 a = *reinterpret_cast<const float4*>(&sA[mm * DIN + k]);
            float4 x = *reinterpret_cast<const float4*>(&sH[mm * DIN + k]);
            float t = acc[mm];
            t = fmaf(a.x, wr0, t); t = fmaf(a.y, wr1, t);
            t = fmaf(a.z, wr2, t); t = fmaf(a.w, wr3, t);
            t = fmaf(x.x, wo0, t); t = fmaf(x.y, wo1, t);
            t = fmaf(x.z, wo2, t); t = fmaf(x.w, wo3, t);
            acc[mm] = t;
        }
    }

    const float scale = __ldg(bng + tid) * rsqrtf(__ldg(bnv + tid) + EPS);
    const float shift = (__ldg(br + tid) - __ldg(bnm + tid)) * scale + __ldg(bnb + tid);
    #pragma unroll
    for (int mm = 0; mm < 32; mm++) {
        float r = fmaf(acc[mm], scale, shift);
        out[(size_t)(n0 + mm) * HIDDEN + tid] = fmaxf(r, 0.f);
    }
}

// ------------- fused mean-pool + head (block per graph) ------------------
// batch is sorted ascending, so each graph's nodes are a contiguous range.
__global__ void pool_head_kernel(const float* __restrict__ h,
                                 const int* __restrict__ batch,
                                 const float* __restrict__ W1,
                                 const float* __restrict__ b1,
                                 const float* __restrict__ W2,
                                 const float* __restrict__ b2,
                                 float* __restrict__ out)
{
    __shared__ float sp[HIDDEN];
    __shared__ float sred[128];
    __shared__ int srange[2];
    const int g = blockIdx.x;
    const int t = threadIdx.x;

    if (t < 2) {
        int key = g + t;                 // lower_bound(batch, key)
        int lo = 0, hi = N_NODES;
        while (lo < hi) {
            int mid = (lo + hi) >> 1;
            if (__ldg(batch + mid) < key) lo = mid + 1; else hi = mid;
        }
        srange[t] = lo;
    }
    __syncthreads();
    const int start = srange[0];
    const int end   = srange[1];

    float sum = 0.f;
    for (int n = start; n < end; n++)
        sum += h[(size_t)n * HIDDEN + t];
    float inv = 1.0f / fmaxf((float)(end - start), 1.0f);
    sp[t] = sum * inv;
    __syncthreads();

    float val = 0.f;
    if (t < 64) {
        float acc = __ldg(b1 + t);
        #pragma unroll 8
        for (int k = 0; k < HIDDEN; k++)
            acc = fmaf(sp[k], __ldg(W1 + k * 64 + t), acc);
        val = fmaxf(acc, 0.f) * __ldg(W2 + t);
    }
    sred[t] = val;
    __syncthreads();
    for (int s = 64; s > 0; s >>= 1) {
        if (t < s) sred[t] += sred[t + s];
        __syncthreads();
    }
    if (t == 0) out[g] = sred[0] + __ldg(b2);
}

// -------------------------------------------------------------------------
extern "C" void kernel_launch(void* const* d_in, const int* in_sizes, int n_in,
                              void* d_out, int out_size)
{
    (void)in_sizes; (void)n_in; (void)out_size;
    const float* x     = (const float*)d_in[0];
    const int*   ei    = (const int*)  d_in[1];
    const float* ea    = (const float*)d_in[2];
    const int*   batch = (const int*)  d_in[3];
    const float* P[21];
    for (int i = 0; i < 21; i++) P[i] = (const float*)d_in[4 + i];
    const float* head_w1 = (const float*)d_in[25];
    const float* head_b1 = (const float*)d_in[26];
    const float* head_w2 = (const float*)d_in[27];
    const float* head_b2 = (const float*)d_in[28];
    float* out = (float*)d_out;

    float *h1, *h2, *agg;
    int *deg, *incl, *bsum, *boff, *rowptr, *cursor, *csr_src;
    float *csr_ew;
    cudaGetSymbolAddress((void**)&h1,      g_h1);
    cudaGetSymbolAddress((void**)&h2,      g_h2);
    cudaGetSymbolAddress((void**)&agg,     g_agg);
    cudaGetSymbolAddress((void**)&deg,     g_deg);
    cudaGetSymbolAddress((void**)&incl,    g_incl);
    cudaGetSymbolAddress((void**)&bsum,    g_bsum);
    cudaGetSymbolAddress((void**)&boff,    g_boff);
    cudaGetSymbolAddress((void**)&rowptr,  g_rowptr);
    cudaGetSymbolAddress((void**)&cursor,  g_cursor);
    cudaGetSymbolAddress((void**)&csr_src, g_csr_src);
    cudaGetSymbolAddress((void**)&csr_ew,  g_csr_ew);

    const int* src = ei;
    const int* dst = ei + N_EDGES;

    // ---- Build CSR by destination ----
    cudaMemsetAsync(deg,    0, N_NODES * sizeof(int), 0);
    cudaMemsetAsync(cursor, 0, N_NODES * sizeof(int), 0);
    hist_kernel<<<(N_EDGES + 255) / 256, 256>>>(dst, deg);
    scan1_kernel<<<N_SCAN_BLOCKS, SCAN_BLK>>>(deg, incl, bsum);
    scan2_kernel<<<1, 512>>>(bsum, boff);
    scan3_kernel<<<(N_NODES + 255) / 256, 256>>>(deg, incl, boff, rowptr);
    fill_kernel<<<(N_EDGES + 255) / 256, 256>>>(src, dst, ea, rowptr, cursor,
                                                csr_src, csr_ew);

    const int gather_blocks = (N_NODES * 32 + 255) / 256;   // warp per node
    const int gemm_blocks   = N_NODES / 32;                 // 3125

    // ---- Layer 0 (DIN = 64): x -> h1 ----
    gather_kernel<64><<<gather_blocks, 256>>>(x, rowptr, csr_src, csr_ew, agg);
    conv_gemm_kernel<64><<<gemm_blocks, 128>>>(agg, x,
        P[0], P[1], P[2], P[3], P[4], P[5], P[6], h1);

    // ---- Layer 1 (DIN = 128): h1 -> h2 ----
    gather_kernel<128><<<gather_blocks, 256>>>(h1, rowptr, csr_src, csr_ew, agg);
    conv_gemm_kernel<128><<<gemm_blocks, 128>>>(agg, h1,
        P[7], P[8], P[9], P[10], P[11], P[12], P[13], h2);

    // ---- Layer 2 (DIN = 128): h2 -> h1 ----
    gather_kernel<128><<<gather_blocks, 256>>>(h2, rowptr, csr_src, csr_ew, agg);
    conv_gemm_kernel<128><<<gemm_blocks, 128>>>(agg, h2,
        P[14], P[15], P[16], P[17], P[18], P[19], P[20], h1);

    // ---- Fused mean pool + head ----
    pool_head_kernel<<<N_GRAPHS, 128>>>(h1, batch, head_w1, head_b1,
                                        head_w2, head_b2, out);
}

// round 3
// speedup vs baseline: 2.7438x; 1.2413x over previous
#include <cuda_runtime.h>
#include <cstddef>

#define N_NODES 100000
#define N_EDGES 1600000
#define F_IN    64
#define HIDDEN  128
#define N_GRAPHS 1024
#define EPS 1e-5f

#define SCAN_BLK 256
#define N_SCAN_BLOCKS ((N_NODES + SCAN_BLK - 1) / SCAN_BLK)   // 391

// ---------------- static scratch (no allocation allowed) ----------------
__device__ float g_hr[(size_t)N_NODES * HIDDEN];      // h @ Wr
__device__ float g_ho[(size_t)N_NODES * HIDDEN];      // h @ Wo
__device__ float g_ha[(size_t)N_NODES * HIDDEN];      // layer activations (ping)
__device__ float g_hb[(size_t)N_NODES * HIDDEN];      // layer activations (pong)

__device__ float g_scale[3][HIDDEN];   // BN folded scale per layer
__device__ float g_shift[3][HIDDEN];   // BN folded shift (incl. rel bias)

__device__ int   g_deg[N_NODES];
__device__ int   g_incl[N_SCAN_BLOCKS * SCAN_BLK];
__device__ int   g_bsum[N_SCAN_BLOCKS];
__device__ int   g_boff[N_SCAN_BLOCKS];
__device__ int   g_rowptr[N_NODES + 1];
__device__ int   g_cursor[N_NODES];
__device__ int   g_csr_src[N_EDGES];
__device__ float g_csr_ew[N_EDGES];

// ======================= CSR build (by dst) ==============================
__global__ void hist_kernel(const int* __restrict__ dst, int* __restrict__ deg)
{
    int e = blockIdx.x * blockDim.x + threadIdx.x;
    if (e < N_EDGES) atomicAdd(deg + __ldg(dst + e), 1);
}

__global__ void scan1_kernel(const int* __restrict__ deg,
                             int* __restrict__ incl, int* __restrict__ bsum)
{
    __shared__ int s[SCAN_BLK];
    int gid = blockIdx.x * SCAN_BLK + threadIdx.x;
    int v = (gid < N_NODES) ? deg[gid] : 0;
    s[threadIdx.x] = v;
    __syncthreads();
    #pragma unroll
    for (int off = 1; off < SCAN_BLK; off <<= 1) {
        int t = (threadIdx.x >= off) ? s[threadIdx.x - off] : 0;
        __syncthreads();
        s[threadIdx.x] += t;
        __syncthreads();
    }
    incl[gid] = s[threadIdx.x];
    if (threadIdx.x == SCAN_BLK - 1) bsum[blockIdx.x] = s[threadIdx.x];
}

__global__ void scan2_kernel(const int* __restrict__ bsum, int* __restrict__ boff)
{
    __shared__ int s[512];
    int t = threadIdx.x;
    s[t] = (t < N_SCAN_BLOCKS) ? bsum[t] : 0;
    __syncthreads();
    #pragma unroll
    for (int off = 1; off < 512; off <<= 1) {
        int v = (t >= off) ? s[t - off] : 0;
        __syncthreads();
        s[t] += v;
        __syncthreads();
    }
    if (t < N_SCAN_BLOCKS) boff[t] = s[t] - bsum[t];   // exclusive
}

__global__ void scan3_kernel(const int* __restrict__ deg,
                             const int* __restrict__ incl,
                             const int* __restrict__ boff,
                             int* __restrict__ rowptr)
{
    int i = blockIdx.x * blockDim.x + threadIdx.x;
    if (i < N_NODES)
        rowptr[i] = incl[i] - deg[i] + boff[i / SCAN_BLK];
    if (i == 0) rowptr[N_NODES] = N_EDGES;
}

__global__ void fill_kernel(const int* __restrict__ src,
                            const int* __restrict__ dst,
                            const float* __restrict__ ew,
                            const int* __restrict__ rowptr,
                            int* __restrict__ cursor,
                            int* __restrict__ csr_src,
                            float* __restrict__ csr_ew)
{
    int e = blockIdx.x * blockDim.x + threadIdx.x;
    if (e >= N_EDGES) return;
    int d = __ldg(dst + e);
    int pos = atomicAdd(cursor + d, 1);
    int idx = __ldg(rowptr + d) + pos;
    csr_src[idx] = __ldg(src + e);
    csr_ew[idx]  = __ldg(ew + e);
}

// ---------------- fold BN params (+rel bias) into scale/shift -------------
__global__ void bn_fold_kernel(const float* __restrict__ br0, const float* __restrict__ g0,
                               const float* __restrict__ b0,  const float* __restrict__ m0,
                               const float* __restrict__ v0,
                               const float* __restrict__ br1, const float* __restrict__ g1,
                               const float* __restrict__ b1,  const float* __restrict__ m1,
                               const float* __restrict__ v1,
                               const float* __restrict__ br2, const float* __restrict__ g2,
                               const float* __restrict__ b2,  const float* __restrict__ m2,
                               const float* __restrict__ v2)
{
    int j = threadIdx.x;           // 0..127
    int l = blockIdx.x;            // 0..2
    const float* br = (l == 0) ? br0 : (l == 1) ? br1 : br2;
    const float* g  = (l == 0) ? g0  : (l == 1) ? g1  : g2;
    const float* b  = (l == 0) ? b0  : (l == 1) ? b1  : b2;
    const float* m  = (l == 0) ? m0  : (l == 1) ? m1  : m2;
    const float* v  = (l == 0) ? v0  : (l == 1) ? v1  : v2;
    float s = g[j] * rsqrtf(v[j] + EPS);
    g_scale[l][j] = s;
    g_shift[l][j] = (br[j] - m[j]) * s + b[j];
}

// ========== dual GEMM: hr = h@Wr, ho = h@Wo (single input tile) ==========
// 128 threads (one per output column), 32-node tile, 1 LDS.128 : 8 FFMA.
template <int K>
__global__ __launch_bounds__(128, 4)
void gemm_dual_kernel(const float* __restrict__ h,
                      const float* __restrict__ Wr,
                      const float* __restrict__ Wo,
                      float* __restrict__ hr,
                      float* __restrict__ ho)
{
    __shared__ float sH[32 * K];
    const int tid = threadIdx.x;
    const int n0  = blockIdx.x * 32;

    {
        const float4* hp = reinterpret_cast<const float4*>(h + (size_t)n0 * K);
        float4* s4 = reinterpret_cast<float4*>(sH);
        #pragma unroll
        for (int i = tid; i < 32 * K / 4; i += 128) s4[i] = hp[i];
    }
    __syncthreads();

    float r[32], o[32];
    #pragma unroll
    for (int mm = 0; mm < 32; mm++) { r[mm] = 0.f; o[mm] = 0.f; }

    #pragma unroll 2
    for (int k = 0; k < K; k += 4) {
        float wr0 = __ldg(Wr + (k + 0) * HIDDEN + tid);
        float wr1 = __ldg(Wr + (k + 1) * HIDDEN + tid);
        float wr2 = __ldg(Wr + (k + 2) * HIDDEN + tid);
        float wr3 = __ldg(Wr + (k + 3) * HIDDEN + tid);
        float wo0 = __ldg(Wo + (k + 0) * HIDDEN + tid);
        float wo1 = __ldg(Wo + (k + 1) * HIDDEN + tid);
        float wo2 = __ldg(Wo + (k + 2) * HIDDEN + tid);
        float wo3 = __ldg(Wo + (k + 3) * HIDDEN + tid);
        #pragma unroll
        for (int mm = 0; mm < 32; mm++) {
            float4 a = *reinterpret_cast<const float4*>(&sH[mm * K + k]);
            float tr = r[mm], to = o[mm];
            tr = fmaf(a.x, wr0, tr); tr = fmaf(a.y, wr1, tr);
            tr = fmaf(a.z, wr2, tr); tr = fmaf(a.w, wr3, tr);
            to = fmaf(a.x, wo0, to); to = fmaf(a.y, wo1, to);
            to = fmaf(a.z, wo2, to); to = fmaf(a.w, wo3, to);
            r[mm] = tr; o[mm] = to;
        }
    }

    #pragma unroll
    for (int mm = 0; mm < 32; mm++) {
        hr[(size_t)(n0 + mm) * HIDDEN + tid] = r[mm];
        ho[(size_t)(n0 + mm) * HIDDEN + tid] = o[mm];
    }
}

// === fused gather + root + BN + ReLU:  out = relu((Σ ew*hr[src] + ho)*s + t)
__global__ void gather_fused_kernel(const float* __restrict__ hr,
                                    const float* __restrict__ ho,
                                    const int* __restrict__ rowptr,
                                    const int* __restrict__ csr_src,
                                    const float* __restrict__ csr_ew,
                                    const float* __restrict__ scale,
                                    const float* __restrict__ shift,
                                    float* __restrict__ out)
{
    int node = (blockIdx.x * blockDim.x + threadIdx.x) >> 5;
    if (node >= N_NODES) return;
    int lane = threadIdx.x & 31;
    int beg = __ldg(rowptr + node);
    int end = __ldg(rowptr + node + 1);

    const float4* hr4 = reinterpret_cast<const float4*>(hr);
    float4 acc = *(reinterpret_cast<const float4*>(ho + (size_t)node * 128) + lane);

    int i = beg;
    for (; i + 3 < end; i += 4) {
        int   s0 = __ldg(csr_src + i);
        int   s1 = __ldg(csr_src + i + 1);
        int   s2 = __ldg(csr_src + i + 2);
        int   s3 = __ldg(csr_src + i + 3);
        float e0 = __ldg(csr_ew + i);
        float e1 = __ldg(csr_ew + i + 1);
        float e2 = __ldg(csr_ew + i + 2);
        float e3 = __ldg(csr_ew + i + 3);
        float4 v0 = hr4[(size_t)s0 * 32 + lane];
        float4 v1 = hr4[(size_t)s1 * 32 + lane];
        float4 v2 = hr4[(size_t)s2 * 32 + lane];
        float4 v3 = hr4[(size_t)s3 * 32 + lane];
        acc.x = fmaf(v0.x, e0, acc.x); acc.y = fmaf(v0.y, e0, acc.y);
        acc.z = fmaf(v0.z, e0, acc.z); acc.w = fmaf(v0.w, e0, acc.w);
        acc.x = fmaf(v1.x, e1, acc.x); acc.y = fmaf(v1.y, e1, acc.y);
        acc.z = fmaf(v1.z, e1, acc.z); acc.w = fmaf(v1.w, e1, acc.w);
        acc.x = fmaf(v2.x, e2, acc.x); acc.y = fmaf(v2.y, e2, acc.y);
        acc.z = fmaf(v2.z, e2, acc.z); acc.w = fmaf(v2.w, e2, acc.w);
        acc.x = fmaf(v3.x, e3, acc.x); acc.y = fmaf(v3.y, e3, acc.y);
        acc.z = fmaf(v3.z, e3, acc.z); acc.w = fmaf(v3.w, e3, acc.w);
    }
    for (; i < end; i++) {
        int   s0 = __ldg(csr_src + i);
        float e0 = __ldg(csr_ew + i);
        float4 v0 = hr4[(size_t)s0 * 32 + lane];
        acc.x = fmaf(v0.x, e0, acc.x); acc.y = fmaf(v0.y, e0, acc.y);
        acc.z = fmaf(v0.z, e0, acc.z); acc.w = fmaf(v0.w, e0, acc.w);
    }

    float4 sc = *(reinterpret_cast<const float4*>(scale) + lane);
    float4 sh = *(reinterpret_cast<const float4*>(shift) + lane);
    float4 res;
    res.x = fmaxf(fmaf(acc.x, sc.x, sh.x), 0.f);
    res.y = fmaxf(fmaf(acc.y, sc.y, sh.y), 0.f);
    res.z = fmaxf(fmaf(acc.z, sc.z, sh.z), 0.f);
    res.w = fmaxf(fmaf(acc.w, sc.w, sh.w), 0.f);
    *(reinterpret_cast<float4*>(out + (size_t)node * 128) + lane) = res;
}

// ------------- fused mean-pool + head (block per graph) ------------------
__global__ void pool_head_kernel(const float* __restrict__ h,
                                 const int* __restrict__ batch,
                                 const float* __restrict__ W1,
                                 const float* __restrict__ b1,
                                 const float* __restrict__ W2,
                                 const float* __restrict__ b2,
                                 float* __restrict__ out)
{
    __shared__ float sp[HIDDEN];
    __shared__ float sred[128];
    __shared__ int srange[2];
    const int g = blockIdx.x;
    const int t = threadIdx.x;

    if (t < 2) {
        int key = g + t;
        int lo = 0, hi = N_NODES;
        while (lo < hi) {
            int mid = (lo + hi) >> 1;
            if (__ldg(batch + mid) < key) lo = mid + 1; else hi = mid;
        }
        srange[t] = lo;
    }
    __syncthreads();
    const int start = srange[0];
    const int end   = srange[1];

    float sum = 0.f;
    for (int n = start; n < end; n++)
        sum += h[(size_t)n * HIDDEN + t];
    float inv = 1.0f / fmaxf((float)(end - start), 1.0f);
    sp[t] = sum * inv;
    __syncthreads();

    float val = 0.f;
    if (t < 64) {
        float acc = __ldg(b1 + t);
        #pragma unroll 8
        for (int k = 0; k < HIDDEN; k++)
            acc = fmaf(sp[k], __ldg(W1 + k * 64 + t), acc);
        val = fmaxf(acc, 0.f) * __ldg(W2 + t);
    }
    sred[t] = val;
    __syncthreads();
    for (int s = 64; s > 0; s >>= 1) {
        if (t < s) sred[t] += sred[t + s];
        __syncthreads();
    }
    if (t == 0) out[g] = sred[0] + __ldg(b2);
}

// -------------------------------------------------------------------------
extern "C" void kernel_launch(void* const* d_in, const int* in_sizes, int n_in,
                              void* d_out, int out_size)
{
    (void)in_sizes; (void)n_in; (void)out_size;
    const float* x     = (const float*)d_in[0];
    const int*   ei    = (const int*)  d_in[1];
    const float* ea    = (const float*)d_in[2];
    const int*   batch = (const int*)  d_in[3];
    const float* P[21];
    for (int i = 0; i < 21; i++) P[i] = (const float*)d_in[4 + i];
    const float* head_w1 = (const float*)d_in[25];
    const float* head_b1 = (const float*)d_in[26];
    const float* head_w2 = (const float*)d_in[27];
    const float* head_b2 = (const float*)d_in[28];
    float* out = (float*)d_out;

    float *hr, *ho, *ha, *hb, *scale, *shift;
    int *deg, *incl, *bsum, *boff, *rowptr, *cursor, *csr_src;
    float *csr_ew;
    cudaGetSymbolAddress((void**)&hr,      g_hr);
    cudaGetSymbolAddress((void**)&ho,      g_ho);
    cudaGetSymbolAddress((void**)&ha,      g_ha);
    cudaGetSymbolAddress((void**)&hb,      g_hb);
    cudaGetSymbolAddress((void**)&scale,   g_scale);
    cudaGetSymbolAddress((void**)&shift,   g_shift);
    cudaGetSymbolAddress((void**)&deg,     g_deg);
    cudaGetSymbolAddress((void**)&incl,    g_incl);
    cudaGetSymbolAddress((void**)&bsum,    g_bsum);
    cudaGetSymbolAddress((void**)&boff,    g_boff);
    cudaGetSymbolAddress((void**)&rowptr,  g_rowptr);
    cudaGetSymbolAddress((void**)&cursor,  g_cursor);
    cudaGetSymbolAddress((void**)&csr_src, g_csr_src);
    cudaGetSymbolAddress((void**)&csr_ew,  g_csr_ew);

    const int* src = ei;
    const int* dst = ei + N_EDGES;

    // ---- Build CSR by destination + fold BN params ----
    cudaMemsetAsync(deg,    0, N_NODES * sizeof(int), 0);
    cudaMemsetAsync(cursor, 0, N_NODES * sizeof(int), 0);
    hist_kernel<<<(N_EDGES + 255) / 256, 256>>>(dst, deg);
    scan1_kernel<<<N_SCAN_BLOCKS, SCAN_BLK>>>(deg, incl, bsum);
    scan2_kernel<<<1, 512>>>(bsum, boff);
    scan3_kernel<<<(N_NODES + 255) / 256, 256>>>(deg, incl, boff, rowptr);
    fill_kernel<<<(N_EDGES + 255) / 256, 256>>>(src, dst, ea, rowptr, cursor,
                                                csr_src, csr_ew);
    bn_fold_kernel<<<3, 128>>>(P[1], P[3], P[4], P[5], P[6],
                               P[8], P[10], P[11], P[12], P[13],
                               P[15], P[17], P[18], P[19], P[20]);

    const int gather_blocks = (N_NODES * 32 + 255) / 256;   // warp per node
    const int gemm_blocks   = N_NODES / 32;                 // 3125

    // ---- Layer 0: x(64) -> hr,ho -> gather -> ha ----
    gemm_dual_kernel<64><<<gemm_blocks, 128>>>(x, P[0], P[2], hr, ho);
    gather_fused_kernel<<<gather_blocks, 256>>>(hr, ho, rowptr, csr_src, csr_ew,
                                                scale + 0 * HIDDEN, shift + 0 * HIDDEN, ha);

    // ---- Layer 1: ha(128) -> hr,ho -> gather -> hb ----
    gemm_dual_kernel<128><<<gemm_blocks, 128>>>(ha, P[7], P[9], hr, ho);
    gather_fused_kernel<<<gather_blocks, 256>>>(hr, ho, rowptr, csr_src, csr_ew,
                                                scale + 1 * HIDDEN, shift + 1 * HIDDEN, hb);

    // ---- Layer 2: hb(128) -> hr,ho -> gather -> ha ----
    gemm_dual_kernel<128><<<gemm_blocks, 128>>>(hb, P[14], P[16], hr, ho);
    gather_fused_kernel<<<gather_blocks, 256>>>(hr, ho, rowptr, csr_src, csr_ew,
                                                scale + 2 * HIDDEN, shift + 2 * HIDDEN, ha);

    // ---- Fused mean pool + head ----
    pool_head_kernel<<<N_GRAPHS, 128>>>(ha, batch, head_w1, head_b1,
                                        head_w2, head_b2, out);
}